// round 7
// baseline (speedup 1.0000x reference)
#include <cuda_runtime.h>
#include <cstdint>
#include <cstddef>

#define B_ 256
#define T_ 2048
#define I_ 128
#define H_ 64
#define G_ 256          // 4*H
#define M_ (B_*T_)      // 524288

// Scratch (device globals: allocation-free rule)
__device__ float g_pre[(size_t)M_ * G_];   // 512 MB
__device__ float g_h0 [(size_t)M_ * H_];   // 128 MB
__device__ float g_h1 [(size_t)M_ * H_];   // 128 MB

// ---------------------------------------------------------------- helpers
__device__ __forceinline__ float to_tf32(float x){
    unsigned u; asm("cvt.rna.tf32.f32 %0, %1;" : "=r"(u) : "f"(x));
    return __uint_as_float(u);
}

__device__ __forceinline__ void mma_tf32(float c[4], const unsigned a[4],
                                         unsigned b0, unsigned b1){
    asm volatile("mma.sync.aligned.m16n8k8.row.col.f32.tf32.tf32.f32 "
        "{%0,%1,%2,%3},{%4,%5,%6,%7},{%8,%9},{%0,%1,%2,%3};"
        : "+f"(c[0]),"+f"(c[1]),"+f"(c[2]),"+f"(c[3])
        : "r"(a[0]),"r"(a[1]),"r"(a[2]),"r"(a[3]),"r"(b0),"r"(b1));
}

__device__ __forceinline__ float sigmoid_f(float x){
    return __fdividef(1.f, 1.f + __expf(-x));
}

// ---------------------------------------------------------------- pre-GEMM
template<int K>
__global__ void __launch_bounds__(256,1)
gemm_pre(const float* __restrict__ A, const float* __restrict__ W,
         const float* __restrict__ b_ih, const float* __restrict__ b_hh,
         float* __restrict__ out)
{
    constexpr int BM = 128, N = G_, KP = K + 4;
    extern __shared__ float sm[];
    float* As = sm;                 // BM x KP
    float* Ws = sm + BM*KP;         // N x KP
    float* bs = Ws + N*KP;          // N

    const int tid = threadIdx.x;
    const size_t m0 = (size_t)blockIdx.x * BM;

    const float4* Ag = (const float4*)(A + m0*(size_t)K);
    for (int i = tid; i < BM*K/4; i += 256){
        float4 v = Ag[i];
        int fi = i*4, row = fi / K, col = fi % K;
        *(float4*)(As + row*KP + col) =
            make_float4(to_tf32(v.x), to_tf32(v.y), to_tf32(v.z), to_tf32(v.w));
    }
    const float4* Wg = (const float4*)W;
    for (int i = tid; i < N*K/4; i += 256){
        float4 v = Wg[i];
        int fi = i*4, row = fi / K, col = fi % K;
        *(float4*)(Ws + row*KP + col) =
            make_float4(to_tf32(v.x), to_tf32(v.y), to_tf32(v.z), to_tf32(v.w));
    }
    bs[tid] = b_ih[tid] + b_hh[tid];
    __syncthreads();

    const int warp = tid >> 5, lane = tid & 31;
    const int wm = warp >> 1, wn = warp & 1;
    const int gid = lane >> 2, tig = lane & 3;

    float c[2][16][4];
    #pragma unroll
    for (int a = 0; a < 2; a++)
        #pragma unroll
        for (int b = 0; b < 16; b++)
            #pragma unroll
            for (int d = 0; d < 4; d++) c[a][b][d] = 0.f;

    #pragma unroll
    for (int ks = 0; ks < K/8; ++ks){
        unsigned af[2][4];
        #pragma unroll
        for (int mt = 0; mt < 2; mt++){
            int r  = wm*32 + mt*16 + gid;
            int cc = ks*8 + tig;
            af[mt][0] = __float_as_uint(As[r*KP + cc]);
            af[mt][1] = __float_as_uint(As[(r+8)*KP + cc]);
            af[mt][2] = __float_as_uint(As[r*KP + cc + 4]);
            af[mt][3] = __float_as_uint(As[(r+8)*KP + cc + 4]);
        }
        #pragma unroll
        for (int nt = 0; nt < 16; nt++){
            int n  = wn*128 + nt*8 + gid;
            int kk = ks*8 + tig;
            unsigned b0 = __float_as_uint(Ws[n*KP + kk]);
            unsigned b1 = __float_as_uint(Ws[n*KP + kk + 4]);
            mma_tf32(c[0][nt], af[0], b0, b1);
            mma_tf32(c[1][nt], af[1], b0, b1);
        }
    }

    #pragma unroll
    for (int mt = 0; mt < 2; mt++){
        size_t r = m0 + wm*32 + mt*16 + gid;
        #pragma unroll
        for (int nt = 0; nt < 16; nt++){
            int col = wn*128 + nt*8 + 2*tig;
            float bb0 = bs[col], bb1 = bs[col+1];
            *(float2*)(out + r*N + col)
                = make_float2(c[mt][nt][0] + bb0, c[mt][nt][1] + bb1);
            *(float2*)(out + (r+8)*N + col)
                = make_float2(c[mt][nt][2] + bb0, c[mt][nt][3] + bb1);
        }
    }
}

// ---------------------------------------------------------------- LSTM scan
// Block = ONE sequence, 512 threads: tid -> (cell j = tid>>3, gate gt =
// (tid>>1)&3, K-half kh = tid&1). The 8 lanes of a cell are adjacent in one
// warp: dot halves combine via shfl.xor(1); gate gather via shfl from lanes
// lbase+{0,2,4,6}. 16 packed weight u64 per thread (32 regs) -> ~60 regs
// total, 2 blocks/SM = 32 warps (2x R6 latency-hiding). ONE barrier/step
// (h_s double-buffered). Activations branch-free via sigmoid identity.
__global__ void __launch_bounds__(512,2)
lstm_scan(const float* __restrict__ pre, const float* __restrict__ w_hh,
          float* __restrict__ h_out)
{
    __shared__ __align__(16) float h_s[2][H_];   // double buffer

    const int tid = threadIdx.x;
    const int j   = tid >> 3;          // cell 0..63
    const int gt  = (tid >> 1) & 3;    // 0=i 1=f 2=g 3=o
    const int kh  = tid & 1;           // K-half
    const int grow = gt * H_ + j;      // row in w_hh / column in pre
    const int b   = blockIdx.x;

    // branch-free activation constants: gt==2 -> tanh via 2*sigmoid(2x)-1
    const float am = (gt == 2) ? 2.f : 1.f;
    const float ab = (gt == 2) ? -1.f : 0.f;

    if (tid < 2*H_) ((float*)h_s)[tid] = 0.f;

    // 16 packed weight pairs for this K-half: wpk[m] = {w[kh*32+2m], w[kh*32+2m+1]}
    unsigned long long wpk[16];
    {
        const float4* wr = (const float4*)(w_hh + grow*H_ + kh*32);
        #pragma unroll
        for (int k4 = 0; k4 < 8; k4++){
            float4 v = wr[k4];
            asm("mov.b64 %0,{%1,%2};" : "=l"(wpk[2*k4+0]) : "f"(v.x), "f"(v.y));
            asm("mov.b64 %0,{%1,%2};" : "=l"(wpk[2*k4+1]) : "f"(v.z), "f"(v.w));
        }
    }

    // pre pointer + distance-2 prefetch (both kh lanes load same addr -> merged)
    const float* pp = pre + ((size_t)b * T_) * G_ + grow;
    float p0 = pp[0];
    float p1 = pp[G_];

    float creg = 0.f;                          // cell state (8 redundant copies)
    const unsigned lbase = (tid & 31) & ~7u;   // first lane of this cell group

    __syncthreads();

    for (int t = 0; t < T_; ++t){
        int tp = (t + 2 < T_) ? t + 2 : T_ - 1;
        float pn = __ldg(pp + (size_t)tp * G_);

        const int rb = t & 1;
        // half-matvec: 16 FFMA2 in 4 chains of 4
        unsigned long long a0, a1, a2, a3;
        asm("mov.b64 %0,{%1,%2};" : "=l"(a0) : "f"(0.f), "f"(0.f));
        asm("mov.b64 %0,{%1,%2};" : "=l"(a1) : "f"(0.f), "f"(0.f));
        asm("mov.b64 %0,{%1,%2};" : "=l"(a2) : "f"(0.f), "f"(0.f));
        asm("mov.b64 %0,{%1,%2};" : "=l"(a3) : "f"(0.f), "f"(0.f));

        const ulonglong2* hv = ((const ulonglong2*)h_s[rb]) + kh*8;
        #pragma unroll
        for (int i = 0; i < 4; i++){
            ulonglong2 x = hv[2*i];
            ulonglong2 y = hv[2*i+1];
            asm("fma.rn.f32x2 %0, %1, %2, %0;" : "+l"(a0) : "l"(wpk[4*i+0]), "l"(x.x));
            asm("fma.rn.f32x2 %0, %1, %2, %0;" : "+l"(a1) : "l"(wpk[4*i+1]), "l"(x.y));
            asm("fma.rn.f32x2 %0, %1, %2, %0;" : "+l"(a2) : "l"(wpk[4*i+2]), "l"(y.x));
            asm("fma.rn.f32x2 %0, %1, %2, %0;" : "+l"(a3) : "l"(wpk[4*i+3]), "l"(y.y));
        }
        unsigned long long s01, s23, s;
        asm("add.rn.f32x2 %0, %1, %2;" : "=l"(s01) : "l"(a0), "l"(a1));
        asm("add.rn.f32x2 %0, %1, %2;" : "=l"(s23) : "l"(a2), "l"(a3));
        asm("add.rn.f32x2 %0, %1, %2;" : "=l"(s)   : "l"(s01), "l"(s23));
        float sl, sh;
        asm("mov.b64 {%0,%1}, %2;" : "=f"(sl), "=f"(sh) : "l"(s));
        float d = sl + sh;                       // this K-half's partial
        d += __shfl_xor_sync(0xffffffffu, d, 1); // combine K-halves
        float a = p0 + d;                        // gate pre-activation

        // branch-free activation (both kh lanes hold identical v)
        float v = fmaf(sigmoid_f(a * am), am, ab);

        // gather the 4 gates of cell j from kh==0 lanes of each pair
        float iv = __shfl_sync(0xffffffffu, v, lbase + 0, 32);
        float fv = __shfl_sync(0xffffffffu, v, lbase + 2, 32);
        float gv = __shfl_sync(0xffffffffu, v, lbase + 4, 32);
        float ov = __shfl_sync(0xffffffffu, v, lbase + 6, 32);

        // cell update (8 redundant copies per cell)
        creg = fmaf(fv, creg, iv * gv);
        float th = fmaf(sigmoid_f(2.f * creg), 2.f, -1.f);   // tanh(c)
        float h  = ov * th;

        if ((tid & 7) == 0){
            h_s[rb ^ 1][j] = h;
            h_out[((size_t)b * T_ + t) * H_ + j] = h;
        }
        p0 = p1; p1 = pn;
        __syncthreads();
    }
}

// ---------------------------------------------------------------- FC head
__global__ void fc_kernel(const float* __restrict__ h, const float* __restrict__ fw,
                          const float* __restrict__ fb, float* __restrict__ out)
{
    size_t m = (size_t)blockIdx.x * blockDim.x + threadIdx.x;
    const float4* hv = (const float4*)(h + m * H_);
    float acc = 0.f;
    #pragma unroll
    for (int i = 0; i < H_/4; i++){
        float4 a = hv[i];
        float4 w = __ldg(((const float4*)fw) + i);
        acc = fmaf(a.x, w.x, fmaf(a.y, w.y, fmaf(a.z, w.z, fmaf(a.w, w.w, acc))));
    }
    out[m] = acc + __ldg(fb);
}

// ---------------------------------------------------------------- launch
extern "C" void kernel_launch(void* const* d_in, const int* in_sizes, int n_in,
                              void* d_out, int out_size)
{
    const float* x     = (const float*)d_in[0];
    const float* w_ih0 = (const float*)d_in[1];
    const float* w_hh0 = (const float*)d_in[2];
    const float* b_ih0 = (const float*)d_in[3];
    const float* b_hh0 = (const float*)d_in[4];
    const float* w_ih1 = (const float*)d_in[5];
    const float* w_hh1 = (const float*)d_in[6];
    const float* b_ih1 = (const float*)d_in[7];
    const float* b_hh1 = (const float*)d_in[8];
    const float* w_ih2 = (const float*)d_in[9];
    const float* w_hh2 = (const float*)d_in[10];
    const float* b_ih2 = (const float*)d_in[11];
    const float* b_hh2 = (const float*)d_in[12];
    const float* fc_w  = (const float*)d_in[13];
    const float* fc_b  = (const float*)d_in[14];
    float* out = (float*)d_out;

    float *pre, *h0, *h1;
    cudaGetSymbolAddress((void**)&pre, g_pre);
    cudaGetSymbolAddress((void**)&h0,  g_h0);
    cudaGetSymbolAddress((void**)&h1,  g_h1);

    const int smem128 = (128+256)*(128+4)*4 + 256*4;
    const int smem64  = (128+256)*(64+4)*4  + 256*4;
    cudaFuncSetAttribute(gemm_pre<128>, cudaFuncAttributeMaxDynamicSharedMemorySize, smem128);
    cudaFuncSetAttribute(gemm_pre<64>,  cudaFuncAttributeMaxDynamicSharedMemorySize, smem64);

    gemm_pre<128><<<M_/128, 256, smem128>>>(x,  w_ih0, b_ih0, b_hh0, pre);
    lstm_scan    <<<B_,     512>>>(pre, w_hh0, h0);
    gemm_pre<64> <<<M_/128, 256, smem64 >>>(h0, w_ih1, b_ih1, b_hh1, pre);
    lstm_scan    <<<B_,     512>>>(pre, w_hh1, h1);
    gemm_pre<64> <<<M_/128, 256, smem64 >>>(h1, w_ih2, b_ih2, b_hh2, pre);
    lstm_scan    <<<B_,     512>>>(pre, w_hh2, h0);
    fc_kernel    <<<M_/256, 256>>>(h0, fc_w, fc_b, out);
}

// round 8
// speedup vs baseline: 1.6360x; 1.6360x over previous
#include <cuda_runtime.h>
#include <cstdint>
#include <cstddef>

#define B_ 256
#define T_ 2048
#define I_ 128
#define H_ 64
#define G_ 256          // 4*H
#define M_ (B_*T_)      // 524288

// Scratch (device globals: allocation-free rule)
__device__ float g_pre[(size_t)M_ * G_];   // 512 MB
__device__ float g_h0 [(size_t)M_ * H_];   // 128 MB
__device__ float g_h1 [(size_t)M_ * H_];   // 128 MB

// ---------------------------------------------------------------- helpers
__device__ __forceinline__ void mma_tf32(float c[4], const unsigned a[4],
                                         unsigned b0, unsigned b1){
    asm volatile("mma.sync.aligned.m16n8k8.row.col.f32.tf32.tf32.f32 "
        "{%0,%1,%2,%3},{%4,%5,%6,%7},{%8,%9},{%0,%1,%2,%3};"
        : "+f"(c[0]),"+f"(c[1]),"+f"(c[2]),"+f"(c[3])
        : "r"(a[0]),"r"(a[1]),"r"(a[2]),"r"(a[3]),"r"(b0),"r"(b1));
}

__device__ __forceinline__ float sigmoid_f(float x){
    return __fdividef(1.f, 1.f + __expf(-x));
}

__device__ __forceinline__ unsigned smaddr(const void* p){
    return (unsigned)__cvta_generic_to_shared(p);
}
__device__ __forceinline__ void cp16(unsigned dst, const void* src){
    asm volatile("cp.async.cg.shared.global [%0], [%1], 16;" :: "r"(dst), "l"(src));
}

// ---------------------------------------------------------------- pre-GEMM
// pre[m,g] = A[m,:] . W[g,:] + (b_ih+b_hh)[g], tf32 tensor cores.
// 512 threads, BM=128, N=256, K chunked by 32, cp.async double buffer.
// Warp tile: 32 rows x 64 cols (wm = warp>>2, wn = warp&3).
#define KC 32
#define KP 36                       // 32 + 4 pad: conflict-free frag loads
#define STAGE_F (128*KP + 256*KP)   // floats per stage = 13824

template<int K>
__global__ void __launch_bounds__(512,1)
gemm_pre(const float* __restrict__ A, const float* __restrict__ W,
         const float* __restrict__ b_ih, const float* __restrict__ b_hh,
         float* __restrict__ out)
{
    extern __shared__ float sm[];
    float* bs = sm + 2*STAGE_F;     // 256 bias values

    const int tid = threadIdx.x;
    const size_t m0 = (size_t)blockIdx.x * 128;

    if (tid < 256) bs[tid] = b_ih[tid] + b_hh[tid];

    auto copy_chunk = [&](int c, int st){
        float* Asd = sm + st*STAGE_F;
        float* Wsd = Asd + 128*KP;
        #pragma unroll
        for (int i = tid; i < 128*8; i += 512){
            int row = i >> 3, seg = i & 7;
            cp16(smaddr(Asd + row*KP + seg*4),
                 A + (m0 + row)*(size_t)K + c*KC + seg*4);
        }
        #pragma unroll
        for (int i = tid; i < 256*8; i += 512){
            int row = i >> 3, seg = i & 7;
            cp16(smaddr(Wsd + row*KP + seg*4),
                 W + (size_t)row*K + c*KC + seg*4);
        }
    };

    const int warp = tid >> 5, lane = tid & 31;
    const int wm = warp >> 2, wn = warp & 3;   // 4 m-groups x 4 n-quarters
    const int gid = lane >> 2, tig = lane & 3;

    float acc[2][8][4];
    #pragma unroll
    for (int a = 0; a < 2; a++)
        #pragma unroll
        for (int b = 0; b < 8; b++)
            #pragma unroll
            for (int d = 0; d < 4; d++) acc[a][b][d] = 0.f;

    constexpr int NCH = K / KC;

    copy_chunk(0, 0);
    asm volatile("cp.async.commit_group;");

    for (int c = 0; c < NCH; ++c){
        if (c + 1 < NCH){
            copy_chunk(c + 1, (c + 1) & 1);
            asm volatile("cp.async.commit_group;");
            asm volatile("cp.async.wait_group 1;");
        } else {
            asm volatile("cp.async.wait_group 0;");
        }
        __syncthreads();

        const float* As = sm + (c & 1)*STAGE_F;
        const float* Ws = As + 128*KP;

        #pragma unroll
        for (int ks = 0; ks < KC/8; ++ks){
            const int cc = ks*8 + tig;
            unsigned af[2][4];
            #pragma unroll
            for (int mt = 0; mt < 2; mt++){
                int r = wm*32 + mt*16 + gid;
                af[mt][0] = __float_as_uint(As[r*KP + cc]);
                af[mt][1] = __float_as_uint(As[(r+8)*KP + cc]);
                af[mt][2] = __float_as_uint(As[r*KP + cc + 4]);
                af[mt][3] = __float_as_uint(As[(r+8)*KP + cc + 4]);
            }
            #pragma unroll
            for (int nt = 0; nt < 8; nt++){
                int n = wn*64 + nt*8 + gid;
                unsigned b0 = __float_as_uint(Ws[n*KP + cc]);
                unsigned b1 = __float_as_uint(Ws[n*KP + cc + 4]);
                mma_tf32(acc[0][nt], af[0], b0, b1);
                mma_tf32(acc[1][nt], af[1], b0, b1);
            }
        }
        __syncthreads();
    }

    #pragma unroll
    for (int mt = 0; mt < 2; mt++){
        size_t r = m0 + wm*32 + mt*16 + gid;
        #pragma unroll
        for (int nt = 0; nt < 8; nt++){
            int col = wn*64 + nt*8 + 2*tig;
            float bb0 = bs[col], bb1 = bs[col+1];
            *(float2*)(out + r*G_ + col)
                = make_float2(acc[mt][nt][0] + bb0, acc[mt][nt][1] + bb1);
            *(float2*)(out + (r+8)*G_ + col)
                = make_float2(acc[mt][nt][2] + bb0, acc[mt][nt][3] + bb1);
        }
    }
}

// ---------------------------------------------------------------- LSTM scan
// (R6 exact — best measured: 969 us.) Block = ONE sequence, 256 threads.
// tid -> (j = tid>>2, gt = tid&3): 4 gates of cell j in 4 adjacent lanes,
// gate exchange via shfl, ONE barrier/step, double-buffered h_s, K-paired
// weights in registers, branch-free activations, 2 blocks/SM.
__global__ void __launch_bounds__(256,2)
lstm_scan(const float* __restrict__ pre, const float* __restrict__ w_hh,
          float* __restrict__ h_out)
{
    __shared__ __align__(16) float h_s[2][H_];   // double buffer

    const int tid = threadIdx.x;
    const int j   = tid >> 2;          // cell 0..63
    const int gt  = tid & 3;           // 0=i 1=f 2=g 3=o
    const int grow = gt * H_ + j;      // row in w_hh / column in pre
    const int b   = blockIdx.x;

    const float am = (gt == 2) ? 2.f : 1.f;
    const float ab = (gt == 2) ? -1.f : 0.f;

    if (tid < 2*H_) ((float*)h_s)[tid] = 0.f;

    unsigned long long wpk[32];
    {
        const float4* wr = (const float4*)(w_hh + grow*H_);
        #pragma unroll
        for (int k4 = 0; k4 < 16; k4++){
            float4 v = wr[k4];
            asm("mov.b64 %0,{%1,%2};" : "=l"(wpk[2*k4+0]) : "f"(v.x), "f"(v.y));
            asm("mov.b64 %0,{%1,%2};" : "=l"(wpk[2*k4+1]) : "f"(v.z), "f"(v.w));
        }
    }

    const float* pp = pre + ((size_t)b * T_) * G_ + grow;
    float p0 = pp[0];
    float p1 = pp[G_];

    float creg = 0.f;
    const unsigned lbase = (tid & 31) & ~3u;

    __syncthreads();

    for (int t = 0; t < T_; ++t){
        int tp = (t + 2 < T_) ? t + 2 : T_ - 1;
        float pn = __ldg(pp + (size_t)tp * G_);

        const int rb = t & 1;
        unsigned long long a0, a1, a2, a3;
        asm("mov.b64 %0,{%1,%2};" : "=l"(a0) : "f"(p0),  "f"(0.f));
        asm("mov.b64 %0,{%1,%2};" : "=l"(a1) : "f"(0.f), "f"(0.f));
        asm("mov.b64 %0,{%1,%2};" : "=l"(a2) : "f"(0.f), "f"(0.f));
        asm("mov.b64 %0,{%1,%2};" : "=l"(a3) : "f"(0.f), "f"(0.f));

        const ulonglong2* hv = (const ulonglong2*)h_s[rb];
        #pragma unroll
        for (int i = 0; i < 8; i++){
            ulonglong2 x = hv[i];
            ulonglong2 y = hv[i+8];
            asm("fma.rn.f32x2 %0, %1, %2, %0;" : "+l"(a0) : "l"(wpk[2*i+0]),  "l"(x.x));
            asm("fma.rn.f32x2 %0, %1, %2, %0;" : "+l"(a1) : "l"(wpk[2*i+1]),  "l"(x.y));
            asm("fma.rn.f32x2 %0, %1, %2, %0;" : "+l"(a2) : "l"(wpk[2*i+16]), "l"(y.x));
            asm("fma.rn.f32x2 %0, %1, %2, %0;" : "+l"(a3) : "l"(wpk[2*i+17]), "l"(y.y));
        }
        unsigned long long s01, s23, s;
        asm("add.rn.f32x2 %0, %1, %2;" : "=l"(s01) : "l"(a0), "l"(a1));
        asm("add.rn.f32x2 %0, %1, %2;" : "=l"(s23) : "l"(a2), "l"(a3));
        asm("add.rn.f32x2 %0, %1, %2;" : "=l"(s)   : "l"(s01), "l"(s23));
        float sl, sh;
        asm("mov.b64 {%0,%1}, %2;" : "=f"(sl), "=f"(sh) : "l"(s));
        float a = sl + sh;

        float v = fmaf(sigmoid_f(a * am), am, ab);

        float iv = __shfl_sync(0xffffffffu, v, lbase + 0, 32);
        float fv = __shfl_sync(0xffffffffu, v, lbase + 1, 32);
        float gv = __shfl_sync(0xffffffffu, v, lbase + 2, 32);
        float ov = __shfl_sync(0xffffffffu, v, lbase + 3, 32);

        creg = fmaf(fv, creg, iv * gv);
        float th = fmaf(sigmoid_f(2.f * creg), 2.f, -1.f);   // tanh(c)
        float h  = ov * th;

        if (gt == 0){
            h_s[rb ^ 1][j] = h;
            h_out[((size_t)b * T_ + t) * H_ + j] = h;
        }
        p0 = p1; p1 = pn;
        __syncthreads();
    }
}

// ---------------------------------------------------------------- FC head
__global__ void fc_kernel(const float* __restrict__ h, const float* __restrict__ fw,
                          const float* __restrict__ fb, float* __restrict__ out)
{
    size_t m = (size_t)blockIdx.x * blockDim.x + threadIdx.x;
    const float4* hv = (const float4*)(h + m * H_);
    float acc = 0.f;
    #pragma unroll
    for (int i = 0; i < H_/4; i++){
        float4 a = hv[i];
        float4 w = __ldg(((const float4*)fw) + i);
        acc = fmaf(a.x, w.x, fmaf(a.y, w.y, fmaf(a.z, w.z, fmaf(a.w, w.w, acc))));
    }
    out[m] = acc + __ldg(fb);
}

// ---------------------------------------------------------------- launch
extern "C" void kernel_launch(void* const* d_in, const int* in_sizes, int n_in,
                              void* d_out, int out_size)
{
    const float* x     = (const float*)d_in[0];
    const float* w_ih0 = (const float*)d_in[1];
    const float* w_hh0 = (const float*)d_in[2];
    const float* b_ih0 = (const float*)d_in[3];
    const float* b_hh0 = (const float*)d_in[4];
    const float* w_ih1 = (const float*)d_in[5];
    const float* w_hh1 = (const float*)d_in[6];
    const float* b_ih1 = (const float*)d_in[7];
    const float* b_hh1 = (const float*)d_in[8];
    const float* w_ih2 = (const float*)d_in[9];
    const float* w_hh2 = (const float*)d_in[10];
    const float* b_ih2 = (const float*)d_in[11];
    const float* b_hh2 = (const float*)d_in[12];
    const float* fc_w  = (const float*)d_in[13];
    const float* fc_b  = (const float*)d_in[14];
    float* out = (float*)d_out;

    float *pre, *h0, *h1;
    cudaGetSymbolAddress((void**)&pre, g_pre);
    cudaGetSymbolAddress((void**)&h0,  g_h0);
    cudaGetSymbolAddress((void**)&h1,  g_h1);

    const int smemG = (2*STAGE_F + 256) * 4;   // ~111.6 KB
    cudaFuncSetAttribute(gemm_pre<128>, cudaFuncAttributeMaxDynamicSharedMemorySize, smemG);
    cudaFuncSetAttribute(gemm_pre<64>,  cudaFuncAttributeMaxDynamicSharedMemorySize, smemG);

    gemm_pre<128><<<M_/128, 512, smemG>>>(x,  w_ih0, b_ih0, b_hh0, pre);
    lstm_scan    <<<B_,     256>>>(pre, w_hh0, h0);
    gemm_pre<64> <<<M_/128, 512, smemG>>>(h0, w_ih1, b_ih1, b_hh1, pre);
    lstm_scan    <<<B_,     256>>>(pre, w_hh1, h1);
    gemm_pre<64> <<<M_/128, 512, smemG>>>(h1, w_ih2, b_ih2, b_hh2, pre);
    lstm_scan    <<<B_,     256>>>(pre, w_hh2, h0);
    fc_kernel    <<<M_/256, 256>>>(h0, fc_w, fc_b, out);
}